// round 9
// baseline (speedup 1.0000x reference)
#include <cuda_runtime.h>

// ---------------------------------------------------------------------------
// WaveConv2d via perfect-reconstruction identity:
//   out = x + IDWT( mix(level4 coeffs) - level4 coeffs, 0 elsewhere )
// Round 8: dual-accumulator 12-tap loops (halve FMA dependency chains),
// float2 I/O in fusedSyn, anaL4 split across 2 blocks/channel.
// ---------------------------------------------------------------------------

__constant__ float F_H[12] = {
    0.11154074335008017f,  0.4946238903983854f,   0.7511339080215775f,
    0.3152503517092432f,  -0.22626469396516913f, -0.12976686756709563f,
    0.09750160558707936f,  0.02752286553001629f, -0.031582039318031156f,
    0.0005538422009938016f, 0.004777257511010651f, -0.00107730108499558f};

// highpass analysis: F_G[j] = (j odd ? -F_H[11-j] : F_H[11-j])
__constant__ float F_G[12] = {
    -0.00107730108499558f, -0.004777257511010651f, 0.0005538422009938016f,
     0.031582039318031156f, 0.02752286553001629f, -0.09750160558707936f,
    -0.12976686756709563f,  0.22626469396516913f,  0.3152503517092432f,
    -0.7511339080215775f,   0.4946238903983854f,  -0.11154074335008017f};

// lowpass synthesis taps by output parity: even t: F_H[10-2k], odd t: F_H[11-2k]
__constant__ float SYN_C[2][6] = {
    {0.004777257511010651f, -0.031582039318031156f, 0.09750160558707936f,
     -0.22626469396516913f,  0.7511339080215775f,   0.11154074335008017f},
    {-0.00107730108499558f, 0.0005538422009938016f, 0.02752286553001629f,
     -0.12976686756709563f,  0.3152503517092432f,   0.4946238903983854f}};

// highpass synthesis taps: even t: +F_H[2k+1], odd t: -F_H[2k]
__constant__ float SYN_H[2][6] = {
    {0.4946238903983854f,  0.3152503517092432f, -0.12976686756709563f,
     0.02752286553001629f, 0.0005538422009938016f, -0.00107730108499558f},
    {-0.11154074335008017f, -0.7511339080215775f, 0.22626469396516913f,
     -0.09750160558707936f, 0.031582039318031156f, -0.004777257511010651f}};

// scratch (floats)
__device__ float gB[17572864];   // 256*262*262
__device__ float gD[4734976];    // 256*136*136
__device__ float gE[1364224];    // 256*73*73
__device__ float gF[1401856];    // 256*74*74
__device__ float gLL[451584], gLH[451584], gHL[451584], gHH[451584];
__device__ float gML[451584], gMLH[451584], gMHL[451584], gMHH[451584];

__device__ __forceinline__ int refl(int i, int N) {
    if (i < 0) i = -1 - i;
    if (i >= N) i = 2 * N - 1 - i;
    return i;
}

// ---------------------------------------------------------------------------
// Fused lowpass analysis, sliding windows, dual accumulators.
// Tile: 64 out rows x 32 out cols. Dyn smem: sIn[138][75]+sMid[138][33]=59616B
// ---------------------------------------------------------------------------
__global__ void fusedAna(const float* __restrict__ in, float* __restrict__ out,
                         int N, int No) {
    extern __shared__ float sm[];
    float (*sIn)[75]  = (float(*)[75])sm;
    float (*sMid)[33] = (float(*)[33])(sm + 138 * 75);
    const int c0 = blockIdx.x * 32;
    const int t0 = blockIdx.y * 64;
    const int ch = blockIdx.z;
    const int tid = threadIdx.x;
    const float* ip = in + (long)ch * N * N;

    // load 138 x 74 with symmetric reflection
    for (int idx = tid; idx < 138 * 74; idx += 256) {
        int qi = idx / 74, ci = idx % 74;
        int gr = refl(2 * t0 - 10 + qi, N);
        int gc = refl(2 * c0 - 10 + ci, N);
        sIn[qi][ci] = ip[(long)gr * N + gc];
    }
    __syncthreads();

    // width pass: 138 rows x 4 col-groups (8 outputs each), sliding 12-window
    for (int task = tid; task < 138 * 4; task += 256) {
        int q = task >> 2, g = task & 3;
        const float* row = sIn[q] + 16 * g;
        float w[12];
#pragma unroll
        for (int j = 0; j < 10; j++) w[j] = row[j];
#pragma unroll
        for (int c = 0; c < 8; c++) {
            w[(10 + 2 * c) % 12] = row[2 * c + 10];
            w[(11 + 2 * c) % 12] = row[2 * c + 11];
            float a0 = 0.f, a1 = 0.f;
#pragma unroll
            for (int j = 0; j < 12; j += 2) {
                a0 += F_H[j]     * w[(2 * c + j) % 12];
                a1 += F_H[j + 1] * w[(2 * c + j + 1) % 12];
            }
            sMid[q][8 * g + c] = a0 + a1;
        }
    }
    __syncthreads();

    // height pass: 32 cols x 8 strips (8 outputs each), sliding window down
    {
        const int c = tid & 31;
        const int s = tid >> 5;          // 0..7
        const int base = 16 * s;
        float m[12];
#pragma unroll
        for (int j = 0; j < 10; j++) m[j] = sMid[base + j][c];
#pragma unroll
        for (int k = 0; k < 8; k++) {
            m[(10 + 2 * k) % 12] = sMid[base + 10 + 2 * k][c];
            m[(11 + 2 * k) % 12] = sMid[base + 11 + 2 * k][c];
            float a0 = 0.f, a1 = 0.f;
#pragma unroll
            for (int j = 0; j < 12; j += 2) {
                a0 += F_H[j]     * m[(2 * k + j) % 12];
                a1 += F_H[j + 1] * m[(2 * k + j + 1) % 12];
            }
            int t = t0 + 8 * s + k;
            int cg = c0 + c;
            if (t < No && cg < No)
                out[(long)ch * No * No + (long)t * No + cg] = a0 + a1;
        }
    }
}

// ---------------------------------------------------------------------------
// Fused lowpass synthesis, parity-paired, float2 output (+x) path.
// Tile 64x64 out from 37x37 in. in strides (rs, cs) support crop reads.
// ---------------------------------------------------------------------------
__global__ void fusedSyn(const float* __restrict__ in, float* __restrict__ out,
                         const float* __restrict__ x,
                         int N, long rs, long cs, int M) {
    __shared__ float sIn[37][38];
    __shared__ float sMid[64][38];
    const int c0 = blockIdx.x * 64;
    const int r0 = blockIdx.y * 64;
    const int ch = blockIdx.z;
    const int q0 = r0 >> 1, m0 = c0 >> 1;
    const float* ip = in + (long)ch * cs;

    for (int idx = threadIdx.x; idx < 37 * 37; idx += blockDim.x) {
        int qi = idx / 37, mi = idx % 37;
        int q = q0 + qi, m = m0 + mi;
        sIn[qi][mi] = (q < N && m < N) ? ip[(long)q * rs + m] : 0.f;
    }
    __syncthreads();

    // height: 32 row-pairs x 37 cols; pair shares the 6 inputs
    for (int idx = threadIdx.x; idx < 32 * 37; idx += blockDim.x) {
        int s = idx / 37, mi = idx % 37;
        float a0 = 0.f, a1 = 0.f;
#pragma unroll
        for (int k = 0; k < 6; k++) {
            float v = sIn[s + k][mi];
            a0 += SYN_C[0][k] * v;
            a1 += SYN_C[1][k] * v;
        }
        sMid[2 * s][mi] = a0;
        sMid[2 * s + 1][mi] = a1;
    }
    __syncthreads();

    // width: 64 rows x 32 col-pairs, float2 stores (c even, M even)
    for (int idx = threadIdx.x; idx < 64 * 32; idx += blockDim.x) {
        int ti = idx >> 5, s = idx & 31;
        float a0 = 0.f, a1 = 0.f;
#pragma unroll
        for (int k = 0; k < 6; k++) {
            float v = sMid[ti][s + k];
            a0 += SYN_C[0][k] * v;
            a1 += SYN_C[1][k] * v;
        }
        int r = r0 + ti, c = c0 + 2 * s;
        if (r < M && c < M) {
            long o = (long)ch * M * M + (long)r * M + c;
            float2 res;
            if (x) {
                float2 xv = *(const float2*)(x + o);
                res.x = a0 + xv.x;
                res.y = a1 + xv.y;
            } else {
                res.x = a0;
                res.y = a1;
            }
            *(float2*)(out + o) = res;
        }
    }
}

// ---------------------------------------------------------------------------
// Merged L4 analysis, split 2 blocks/channel (row halves of the 42-output dim).
// Block (ch, h): outputs t in [21h, 21h+21). Dyn smem:
// sIn[63][95] + sLo[63][43] + sHi[63][43] = 45632 B.
// ---------------------------------------------------------------------------
__global__ void anaL4(const float* __restrict__ E, float* __restrict__ LL,
                      float* __restrict__ LH, float* __restrict__ HL,
                      float* __restrict__ HH) {
    extern __shared__ float sm[];
    float (*sIn)[95] = (float(*)[95])sm;
    float (*sLo)[43] = (float(*)[43])(sm + 63 * 95);
    float (*sHi)[43] = (float(*)[43])(sm + 63 * 95 + 63 * 43);
    const int ch = blockIdx.x;
    const int h = blockIdx.y;
    const float* ip = E + (long)ch * 73 * 73;

    // load 63 rows x 94 cols: global rows 42h-10 .. 42h+52, cols -10..83 (refl)
    for (int idx = threadIdx.x; idx < 63 * 94; idx += 256) {
        int qi = idx / 94, ci = idx % 94;
        sIn[qi][ci] = ip[refl(42 * h - 10 + qi, 73) * 73 + refl(ci - 10, 73)];
    }
    __syncthreads();

    // width split on 63 rows
    for (int idx = threadIdx.x; idx < 63 * 42; idx += 256) {
        int q = idx / 42, c = idx % 42;
        float l0 = 0.f, l1 = 0.f, h0 = 0.f, h1 = 0.f;
#pragma unroll
        for (int j = 0; j < 12; j += 2) {
            float v0 = sIn[q][2 * c + j];
            float v1 = sIn[q][2 * c + j + 1];
            l0 += F_H[j] * v0;     l1 += F_H[j + 1] * v1;
            h0 += F_G[j] * v0;     h1 += F_G[j + 1] * v1;
        }
        sLo[q][c] = l0 + l1;
        sHi[q][c] = h0 + h1;
    }
    __syncthreads();

    // height split -> 4 subbands (21 out rows this half)
    for (int idx = threadIdx.x; idx < 21 * 42; idx += 256) {
        int tl = idx / 42, c = idx % 42;
        float ll = 0.f, lh = 0.f, hl = 0.f, hh = 0.f;
#pragma unroll
        for (int j = 0; j < 12; j++) {
            float vl = sLo[2 * tl + j][c];
            float vh = sHi[2 * tl + j][c];
            ll += F_H[j] * vl;
            lh += F_G[j] * vl;
            hl += F_H[j] * vh;
            hh += F_G[j] * vh;
        }
        int t = 21 * h + tl;
        long o = (long)ch * 1764 + (long)t * 42 + c;
        LL[o] = ll; LH[o] = lh; HL[o] = hl; HH[o] = hh;
    }
}

// ---------------------------------------------------------------------------
// Merged L4 synthesis: ML,MLH,MHL,MHH (42x42) -> F (74x74). Block per channel.
// ---------------------------------------------------------------------------
__global__ void synL4(const float* __restrict__ ML, const float* __restrict__ MLH,
                      const float* __restrict__ MHL, const float* __restrict__ MHH,
                      float* __restrict__ F) {
    extern __shared__ float sm[];
    float (*sML)[43]  = (float(*)[43])sm;
    float (*sMLH)[43] = (float(*)[43])(sm + 42 * 43);
    float (*sMHL)[43] = (float(*)[43])(sm + 2 * 42 * 43);
    float (*sMHH)[43] = (float(*)[43])(sm + 3 * 42 * 43);
    float (*sLo)[43]  = (float(*)[43])(sm + 4 * 42 * 43);
    float (*sHi)[43]  = (float(*)[43])(sm + 4 * 42 * 43 + 74 * 43);
    const int ch = blockIdx.x;
    const long cb = (long)ch * 1764;

    for (int idx = threadIdx.x; idx < 1764; idx += 256) {
        int r = idx / 42, c = idx % 42;
        sML[r][c]  = ML[cb + idx];
        sMLH[r][c] = MLH[cb + idx];
        sMHL[r][c] = MHL[cb + idx];
        sMHH[r][c] = MHH[cb + idx];
    }
    __syncthreads();

    for (int idx = threadIdx.x; idx < 37 * 42; idx += 256) {
        int s = idx / 42, c = idx % 42;
        float l0 = 0.f, l1 = 0.f, h0 = 0.f, h1 = 0.f;
#pragma unroll
        for (int k = 0; k < 6; k++) {
            float vl = sML[s + k][c],  vlh = sMLH[s + k][c];
            float vh = sMHL[s + k][c], vhh = sMHH[s + k][c];
            l0 += SYN_C[0][k] * vl + SYN_H[0][k] * vlh;
            l1 += SYN_C[1][k] * vl + SYN_H[1][k] * vlh;
            h0 += SYN_C[0][k] * vh + SYN_H[0][k] * vhh;
            h1 += SYN_C[1][k] * vh + SYN_H[1][k] * vhh;
        }
        sLo[2 * s][c] = l0; sLo[2 * s + 1][c] = l1;
        sHi[2 * s][c] = h0; sHi[2 * s + 1][c] = h1;
    }
    __syncthreads();

    for (int idx = threadIdx.x; idx < 74 * 37; idx += 256) {
        int r = idx / 37, s = idx % 37;
        float a0 = 0.f, a1 = 0.f;
#pragma unroll
        for (int k = 0; k < 6; k++) {
            float vl = sLo[r][s + k], vh = sHi[r][s + k];
            a0 += SYN_C[0][k] * vl + SYN_H[0][k] * vh;
            a1 += SYN_C[1][k] * vl + SYN_H[1][k] * vh;
        }
        long o = (long)ch * 74 * 74 + (long)r * 74 + 2 * s;
        F[o] = a0; F[o + 1] = a1;
    }
}

// ---------------------------------------------------------------------------
// Channel mix minus identity, all 4 bands, weights read once from DRAM.
// grid = (7 pixel-chunks, 32 o, 4 bands), 256 threads.
// ---------------------------------------------------------------------------
__global__ void mixAll(const float* __restrict__ LL, const float* __restrict__ LH,
                       const float* __restrict__ HL, const float* __restrict__ HH,
                       float* __restrict__ ML, float* __restrict__ MLH,
                       float* __restrict__ MHL, float* __restrict__ MHH,
                       const float* __restrict__ wyl, const float* __restrict__ wyh) {
    int p = blockIdx.x * 256 + threadIdx.x;
    if (p >= 1764) return;
    int o = blockIdx.y;
    int band = blockIdx.z;
    const float* in; float* outp; const float* w; long ioStride;
    if (band == 0)      { in = LL; outp = ML;  w = wyl;            ioStride = 1764; }
    else if (band == 1) { in = LH; outp = MLH; w = wyh;            ioStride = 5292; }
    else if (band == 2) { in = HL; outp = MHL; w = wyh + 1764;     ioStride = 5292; }
    else                { in = HH; outp = MHH; w = wyh + 2 * 1764; ioStride = 5292; }

    float acc[8];
#pragma unroll
    for (int b = 0; b < 8; b++) acc[b] = -in[((long)b * 32 + o) * 1764 + p];
    for (int i = 0; i < 32; i++) {
        float wv = w[((long)i * 32 + o) * ioStride + p];
#pragma unroll
        for (int b = 0; b < 8; b++)
            acc[b] += in[((long)b * 32 + i) * 1764 + p] * wv;
    }
#pragma unroll
    for (int b = 0; b < 8; b++) outp[((long)b * 32 + o) * 1764 + p] = acc[b];
}

static inline int ceilDiv(int a, int b) { return (a + b - 1) / b; }

extern "C" void kernel_launch(void* const* d_in, const int* in_sizes, int n_in,
                              void* d_out, int out_size) {
    (void)in_sizes; (void)n_in; (void)out_size;
    const float* x   = (const float*)d_in[0];
    const float* wyl = (const float*)d_in[1];
    const float* wyh = (const float*)d_in[2];
    float* out = (float*)d_out;

    float *B,*D,*E,*F,*LL,*LH,*HL,*HH,*ML,*MLH,*MHL,*MHH;
    cudaGetSymbolAddress((void**)&B,  gB);
    cudaGetSymbolAddress((void**)&D,  gD);
    cudaGetSymbolAddress((void**)&E,  gE);
    cudaGetSymbolAddress((void**)&F,  gF);
    cudaGetSymbolAddress((void**)&LL, gLL);
    cudaGetSymbolAddress((void**)&LH, gLH);
    cudaGetSymbolAddress((void**)&HL, gHL);
    cudaGetSymbolAddress((void**)&HH, gHH);
    cudaGetSymbolAddress((void**)&ML, gML);
    cudaGetSymbolAddress((void**)&MLH, gMLH);
    cudaGetSymbolAddress((void**)&MHL, gMHL);
    cudaGetSymbolAddress((void**)&MHH, gMHH);

    const int anaSm   = (138 * 75 + 138 * 33) * 4;          // 59616
    const int anaL4Sm = (63 * 95 + 2 * 63 * 43) * 4;        // 45612
    const int synL4Sm = (4 * 42 * 43 + 2 * 74 * 43) * 4;    // 54352
    cudaFuncSetAttribute(fusedAna, cudaFuncAttributeMaxDynamicSharedMemorySize, anaSm);
    cudaFuncSetAttribute(anaL4,   cudaFuncAttributeMaxDynamicSharedMemorySize, anaL4Sm);
    cudaFuncSetAttribute(synL4,   cudaFuncAttributeMaxDynamicSharedMemorySize, synL4Sm);

    // forward lowpass chain
    fusedAna<<<dim3(ceilDiv(261, 32), ceilDiv(261, 64), 256), 256, anaSm>>>(x, B, 512, 261);
    fusedAna<<<dim3(ceilDiv(136, 32), ceilDiv(136, 64), 256), 256, anaSm>>>(B, D, 261, 136);
    fusedAna<<<dim3(ceilDiv(73, 32),  ceilDiv(73, 64),  256), 256, anaSm>>>(D, E, 136, 73);
    // L4 split (2 blocks per channel)
    anaL4<<<dim3(256, 2), 256, anaL4Sm>>>(E, LL, LH, HL, HH);
    // channel mix (weights read once)
    mixAll<<<dim3(7, 32, 4), 256>>>(LL, LH, HL, HH, ML, MLH, MHL, MHH, wyl, wyh);
    // inverse
    synL4<<<256, 256, synL4Sm>>>(ML, MLH, MHL, MHH, F);
    fusedSyn<<<dim3(ceilDiv(136, 64), ceilDiv(136, 64), 256), 256>>>(
        F, D, nullptr, 73, 74, 74L * 74, 136);
    fusedSyn<<<dim3(ceilDiv(262, 64), ceilDiv(262, 64), 256), 256>>>(
        D, B, nullptr, 136, 136, 136L * 136, 262);
    fusedSyn<<<dim3(ceilDiv(512, 64), ceilDiv(512, 64), 256), 256>>>(
        B, out, x, 261, 262, 262L * 262, 512);
}

// round 11
// speedup vs baseline: 1.4569x; 1.4569x over previous
#include <cuda_runtime.h>

// ---------------------------------------------------------------------------
// WaveConv2d via perfect-reconstruction identity:
//   out = x + IDWT( mix(level4 coeffs) - level4 coeffs, 0 elsewhere )
// Round 11: resubmit of Round-10 (third infra flake, same signature as R4/R6
// which both passed on resubmit). fusedAna 32x32 tile (32KB smem, 7 blocks/SM)
// + float2 loads with even row strides (B:262, E:74); synL4 at 512 threads.
// ---------------------------------------------------------------------------

__constant__ float F_H[12] = {
    0.11154074335008017f,  0.4946238903983854f,   0.7511339080215775f,
    0.3152503517092432f,  -0.22626469396516913f, -0.12976686756709563f,
    0.09750160558707936f,  0.02752286553001629f, -0.031582039318031156f,
    0.0005538422009938016f, 0.004777257511010651f, -0.00107730108499558f};

// highpass analysis: F_G[j] = (j odd ? -F_H[11-j] : F_H[11-j])
__constant__ float F_G[12] = {
    -0.00107730108499558f, -0.004777257511010651f, 0.0005538422009938016f,
     0.031582039318031156f, 0.02752286553001629f, -0.09750160558707936f,
    -0.12976686756709563f,  0.22626469396516913f,  0.3152503517092432f,
    -0.7511339080215775f,   0.4946238903983854f,  -0.11154074335008017f};

// lowpass synthesis taps by output parity: even t: F_H[10-2k], odd t: F_H[11-2k]
__constant__ float SYN_C[2][6] = {
    {0.004777257511010651f, -0.031582039318031156f, 0.09750160558707936f,
     -0.22626469396516913f,  0.7511339080215775f,   0.11154074335008017f},
    {-0.00107730108499558f, 0.0005538422009938016f, 0.02752286553001629f,
     -0.12976686756709563f,  0.3152503517092432f,   0.4946238903983854f}};

// highpass synthesis taps: even t: +F_H[2k+1], odd t: -F_H[2k]
__constant__ float SYN_H[2][6] = {
    {0.4946238903983854f,  0.3152503517092432f, -0.12976686756709563f,
     0.02752286553001629f, 0.0005538422009938016f, -0.00107730108499558f},
    {-0.11154074335008017f, -0.7511339080215775f, 0.22626469396516913f,
     -0.09750160558707936f, 0.031582039318031156f, -0.004777257511010651f}};

// scratch (floats)
__device__ float gB[17572864];   // 256*262*262 (fwd: 261x261 @stride262; inv: 262x262)
__device__ float gD[4734976];    // 256*136*136
__device__ float gE[1401856];    // 256*73x74 (stride 74, chan stride 5476)
__device__ float gF[1401856];    // 256*74*74
__device__ float gLL[451584], gLH[451584], gHL[451584], gHH[451584];
__device__ float gML[451584], gMLH[451584], gMHL[451584], gMHH[451584];

__device__ __forceinline__ int refl(int i, int N) {
    if (i < 0) i = -1 - i;
    if (i >= N) i = 2 * N - 1 - i;
    return i;
}

// ---------------------------------------------------------------------------
// Fused lowpass analysis. Tile: 32 out rows x 32 out cols. 256 threads.
// Dyn smem: sIn[74][76] + sMid[74][33] = 32264 B  (7 blocks/SM).
// in: logical N x N at row stride inRS (even), channel stride inCS.
// out: No x No at row stride outRS, channel stride outCS.
// ---------------------------------------------------------------------------
__global__ void fusedAna(const float* __restrict__ in, float* __restrict__ out,
                         int N, int inRS, long inCS,
                         int No, int outRS, long outCS) {
    extern __shared__ float sm[];
    float (*sIn)[76]  = (float(*)[76])sm;
    float (*sMid)[33] = (float(*)[33])(sm + 74 * 76);
    const int c0 = blockIdx.x * 32;
    const int t0 = blockIdx.y * 32;
    const int ch = blockIdx.z;
    const int tid = threadIdx.x;
    const float* ip = in + (long)ch * inCS;

    const int g0 = 2 * c0 - 10;
    const bool colInterior = (g0 >= 0) && (g0 + 73 < N);

    if (colInterior) {
        // fast path: rows reflected, columns linear; float2 loads (g0 even,
        // inRS even, inCS even => 8B-aligned)
        for (int idx = tid; idx < 74 * 37; idx += 256) {
            int qi = idx / 37, pi = idx % 37;
            int gr = refl(2 * t0 - 10 + qi, N);
            float2 v = *(const float2*)(ip + (long)gr * inRS + g0 + 2 * pi);
            *(float2*)(&sIn[qi][2 * pi]) = v;
        }
    } else {
        for (int idx = tid; idx < 74 * 74; idx += 256) {
            int qi = idx / 74, ci = idx % 74;
            int gr = refl(2 * t0 - 10 + qi, N);
            int gc = refl(g0 + ci, N);
            sIn[qi][ci] = ip[(long)gr * inRS + gc];
        }
    }
    __syncthreads();

    // width pass: 74 rows x 4 col-groups (8 outputs each), sliding 12-window
    for (int task = tid; task < 74 * 4; task += 256) {
        int q = task >> 2, g = task & 3;
        const float* row = sIn[q] + 16 * g;
        float w[12];
#pragma unroll
        for (int j = 0; j < 10; j++) w[j] = row[j];
#pragma unroll
        for (int c = 0; c < 8; c++) {
            w[(10 + 2 * c) % 12] = row[2 * c + 10];
            w[(11 + 2 * c) % 12] = row[2 * c + 11];
            float a0 = 0.f, a1 = 0.f;
#pragma unroll
            for (int j = 0; j < 12; j += 2) {
                a0 += F_H[j]     * w[(2 * c + j) % 12];
                a1 += F_H[j + 1] * w[(2 * c + j + 1) % 12];
            }
            sMid[q][8 * g + c] = a0 + a1;
        }
    }
    __syncthreads();

    // height pass: 32 cols x 8 strips (4 outputs each), sliding window down
    {
        const int c = tid & 31;
        const int s = tid >> 5;          // 0..7
        const int base = 8 * s;
        float m[12];
#pragma unroll
        for (int j = 0; j < 10; j++) m[j] = sMid[base + j][c];
#pragma unroll
        for (int k = 0; k < 4; k++) {
            m[(10 + 2 * k) % 12] = sMid[base + 10 + 2 * k][c];
            m[(11 + 2 * k) % 12] = sMid[base + 11 + 2 * k][c];
            float a0 = 0.f, a1 = 0.f;
#pragma unroll
            for (int j = 0; j < 12; j += 2) {
                a0 += F_H[j]     * m[(2 * k + j) % 12];
                a1 += F_H[j + 1] * m[(2 * k + j + 1) % 12];
            }
            int t = t0 + 4 * s + k;
            int cg = c0 + c;
            if (t < No && cg < No)
                out[(long)ch * outCS + (long)t * outRS + cg] = a0 + a1;
        }
    }
}

// ---------------------------------------------------------------------------
// Fused lowpass synthesis, parity-paired, float2 output (+x) path.
// Tile 64x64 out from 37x37 in. in strides (rs, cs) support crop reads.
// ---------------------------------------------------------------------------
__global__ void fusedSyn(const float* __restrict__ in, float* __restrict__ out,
                         const float* __restrict__ x,
                         int N, long rs, long cs, int M) {
    __shared__ float sIn[37][38];
    __shared__ float sMid[64][38];
    const int c0 = blockIdx.x * 64;
    const int r0 = blockIdx.y * 64;
    const int ch = blockIdx.z;
    const int q0 = r0 >> 1, m0 = c0 >> 1;
    const float* ip = in + (long)ch * cs;

    for (int idx = threadIdx.x; idx < 37 * 37; idx += blockDim.x) {
        int qi = idx / 37, mi = idx % 37;
        int q = q0 + qi, m = m0 + mi;
        sIn[qi][mi] = (q < N && m < N) ? ip[(long)q * rs + m] : 0.f;
    }
    __syncthreads();

    // height: 32 row-pairs x 37 cols; pair shares the 6 inputs
    for (int idx = threadIdx.x; idx < 32 * 37; idx += blockDim.x) {
        int s = idx / 37, mi = idx % 37;
        float a0 = 0.f, a1 = 0.f;
#pragma unroll
        for (int k = 0; k < 6; k++) {
            float v = sIn[s + k][mi];
            a0 += SYN_C[0][k] * v;
            a1 += SYN_C[1][k] * v;
        }
        sMid[2 * s][mi] = a0;
        sMid[2 * s + 1][mi] = a1;
    }
    __syncthreads();

    // width: 64 rows x 32 col-pairs, float2 stores (c even, M even)
    for (int idx = threadIdx.x; idx < 64 * 32; idx += blockDim.x) {
        int ti = idx >> 5, s = idx & 31;
        float a0 = 0.f, a1 = 0.f;
#pragma unroll
        for (int k = 0; k < 6; k++) {
            float v = sMid[ti][s + k];
            a0 += SYN_C[0][k] * v;
            a1 += SYN_C[1][k] * v;
        }
        int r = r0 + ti, c = c0 + 2 * s;
        if (r < M && c < M) {
            long o = (long)ch * M * M + (long)r * M + c;
            float2 res;
            if (x) {
                float2 xv = *(const float2*)(x + o);
                res.x = a0 + xv.x;
                res.y = a1 + xv.y;
            } else {
                res.x = a0;
                res.y = a1;
            }
            *(float2*)(out + o) = res;
        }
    }
}

// ---------------------------------------------------------------------------
// Merged L4 analysis, 2 blocks/channel (row halves). E at row stride 74,
// channel stride 5476. Dyn smem: sIn[63][95]+sLo[63][43]+sHi[63][43]=45612 B.
// ---------------------------------------------------------------------------
__global__ void anaL4(const float* __restrict__ E, float* __restrict__ LL,
                      float* __restrict__ LH, float* __restrict__ HL,
                      float* __restrict__ HH) {
    extern __shared__ float sm[];
    float (*sIn)[95] = (float(*)[95])sm;
    float (*sLo)[43] = (float(*)[43])(sm + 63 * 95);
    float (*sHi)[43] = (float(*)[43])(sm + 63 * 95 + 63 * 43);
    const int ch = blockIdx.x;
    const int h = blockIdx.y;
    const float* ip = E + (long)ch * 5476;

    // load 63 rows x 94 cols: global rows 42h-10 .. 42h+52, cols -10..83 (refl)
    for (int idx = threadIdx.x; idx < 63 * 94; idx += 256) {
        int qi = idx / 94, ci = idx % 94;
        sIn[qi][ci] = ip[(long)refl(42 * h - 10 + qi, 73) * 74 + refl(ci - 10, 73)];
    }
    __syncthreads();

    // width split on 63 rows
    for (int idx = threadIdx.x; idx < 63 * 42; idx += 256) {
        int q = idx / 42, c = idx % 42;
        float l0 = 0.f, l1 = 0.f, h0 = 0.f, h1 = 0.f;
#pragma unroll
        for (int j = 0; j < 12; j += 2) {
            float v0 = sIn[q][2 * c + j];
            float v1 = sIn[q][2 * c + j + 1];
            l0 += F_H[j] * v0;     l1 += F_H[j + 1] * v1;
            h0 += F_G[j] * v0;     h1 += F_G[j + 1] * v1;
        }
        sLo[q][c] = l0 + l1;
        sHi[q][c] = h0 + h1;
    }
    __syncthreads();

    // height split -> 4 subbands (21 out rows this half)
    for (int idx = threadIdx.x; idx < 21 * 42; idx += 256) {
        int tl = idx / 42, c = idx % 42;
        float ll = 0.f, lh = 0.f, hl = 0.f, hh = 0.f;
#pragma unroll
        for (int j = 0; j < 12; j++) {
            float vl = sLo[2 * tl + j][c];
            float vh = sHi[2 * tl + j][c];
            ll += F_H[j] * vl;
            lh += F_G[j] * vl;
            hl += F_H[j] * vh;
            hh += F_G[j] * vh;
        }
        int t = 21 * h + tl;
        long o = (long)ch * 1764 + (long)t * 42 + c;
        LL[o] = ll; LH[o] = lh; HL[o] = hl; HH[o] = hh;
    }
}

// ---------------------------------------------------------------------------
// Merged L4 synthesis: ML,MLH,MHL,MHH (42x42) -> F (74x74). Block/channel,
// 512 threads.
// ---------------------------------------------------------------------------
__global__ void synL4(const float* __restrict__ ML, const float* __restrict__ MLH,
                      const float* __restrict__ MHL, const float* __restrict__ MHH,
                      float* __restrict__ F) {
    extern __shared__ float sm[];
    float (*sML)[43]  = (float(*)[43])sm;
    float (*sMLH)[43] = (float(*)[43])(sm + 42 * 43);
    float (*sMHL)[43] = (float(*)[43])(sm + 2 * 42 * 43);
    float (*sMHH)[43] = (float(*)[43])(sm + 3 * 42 * 43);
    float (*sLo)[43]  = (float(*)[43])(sm + 4 * 42 * 43);
    float (*sHi)[43]  = (float(*)[43])(sm + 4 * 42 * 43 + 74 * 43);
    const int ch = blockIdx.x;
    const long cb = (long)ch * 1764;

    for (int idx = threadIdx.x; idx < 1764; idx += 512) {
        int r = idx / 42, c = idx % 42;
        sML[r][c]  = ML[cb + idx];
        sMLH[r][c] = MLH[cb + idx];
        sMHL[r][c] = MHL[cb + idx];
        sMHH[r][c] = MHH[cb + idx];
    }
    __syncthreads();

    for (int idx = threadIdx.x; idx < 37 * 42; idx += 512) {
        int s = idx / 42, c = idx % 42;
        float l0 = 0.f, l1 = 0.f, h0 = 0.f, h1 = 0.f;
#pragma unroll
        for (int k = 0; k < 6; k++) {
            float vl = sML[s + k][c],  vlh = sMLH[s + k][c];
            float vh = sMHL[s + k][c], vhh = sMHH[s + k][c];
            l0 += SYN_C[0][k] * vl + SYN_H[0][k] * vlh;
            l1 += SYN_C[1][k] * vl + SYN_H[1][k] * vlh;
            h0 += SYN_C[0][k] * vh + SYN_H[0][k] * vhh;
            h1 += SYN_C[1][k] * vh + SYN_H[1][k] * vhh;
        }
        sLo[2 * s][c] = l0; sLo[2 * s + 1][c] = l1;
        sHi[2 * s][c] = h0; sHi[2 * s + 1][c] = h1;
    }
    __syncthreads();

    for (int idx = threadIdx.x; idx < 74 * 37; idx += 512) {
        int r = idx / 37, s = idx % 37;
        float a0 = 0.f, a1 = 0.f;
#pragma unroll
        for (int k = 0; k < 6; k++) {
            float vl = sLo[r][s + k], vh = sHi[r][s + k];
            a0 += SYN_C[0][k] * vl + SYN_H[0][k] * vh;
            a1 += SYN_C[1][k] * vl + SYN_H[1][k] * vh;
        }
        long o = (long)ch * 74 * 74 + (long)r * 74 + 2 * s;
        F[o] = a0; F[o + 1] = a1;
    }
}

// ---------------------------------------------------------------------------
// Channel mix minus identity, all 4 bands, weights read once from DRAM.
// grid = (7 pixel-chunks, 32 o, 4 bands), 256 threads.
// ---------------------------------------------------------------------------
__global__ void mixAll(const float* __restrict__ LL, const float* __restrict__ LH,
                       const float* __restrict__ HL, const float* __restrict__ HH,
                       float* __restrict__ ML, float* __restrict__ MLH,
                       float* __restrict__ MHL, float* __restrict__ MHH,
                       const float* __restrict__ wyl, const float* __restrict__ wyh) {
    int p = blockIdx.x * 256 + threadIdx.x;
    if (p >= 1764) return;
    int o = blockIdx.y;
    int band = blockIdx.z;
    const float* in; float* outp; const float* w; long ioStride;
    if (band == 0)      { in = LL; outp = ML;  w = wyl;            ioStride = 1764; }
    else if (band == 1) { in = LH; outp = MLH; w = wyh;            ioStride = 5292; }
    else if (band == 2) { in = HL; outp = MHL; w = wyh + 1764;     ioStride = 5292; }
    else                { in = HH; outp = MHH; w = wyh + 2 * 1764; ioStride = 5292; }

    float acc[8];
#pragma unroll
    for (int b = 0; b < 8; b++) acc[b] = -in[((long)b * 32 + o) * 1764 + p];
    for (int i = 0; i < 32; i++) {
        float wv = w[((long)i * 32 + o) * ioStride + p];
#pragma unroll
        for (int b = 0; b < 8; b++)
            acc[b] += in[((long)b * 32 + i) * 1764 + p] * wv;
    }
#pragma unroll
    for (int b = 0; b < 8; b++) outp[((long)b * 32 + o) * 1764 + p] = acc[b];
}

static inline int ceilDiv(int a, int b) { return (a + b - 1) / b; }

extern "C" void kernel_launch(void* const* d_in, const int* in_sizes, int n_in,
                              void* d_out, int out_size) {
    (void)in_sizes; (void)n_in; (void)out_size;
    const float* x   = (const float*)d_in[0];
    const float* wyl = (const float*)d_in[1];
    const float* wyh = (const float*)d_in[2];
    float* out = (float*)d_out;

    float *B,*D,*E,*F,*LL,*LH,*HL,*HH,*ML,*MLH,*MHL,*MHH;
    cudaGetSymbolAddress((void**)&B,  gB);
    cudaGetSymbolAddress((void**)&D,  gD);
    cudaGetSymbolAddress((void**)&E,  gE);
    cudaGetSymbolAddress((void**)&F,  gF);
    cudaGetSymbolAddress((void**)&LL, gLL);
    cudaGetSymbolAddress((void**)&LH, gLH);
    cudaGetSymbolAddress((void**)&HL, gHL);
    cudaGetSymbolAddress((void**)&HH, gHH);
    cudaGetSymbolAddress((void**)&ML, gML);
    cudaGetSymbolAddress((void**)&MLH, gMLH);
    cudaGetSymbolAddress((void**)&MHL, gMHL);
    cudaGetSymbolAddress((void**)&MHH, gMHH);

    const int anaSm   = (74 * 76 + 74 * 33) * 4;            // 32264
    const int anaL4Sm = (63 * 95 + 2 * 63 * 43) * 4;        // 45612
    const int synL4Sm = (4 * 42 * 43 + 2 * 74 * 43) * 4;    // 54352
    cudaFuncSetAttribute(fusedAna, cudaFuncAttributeMaxDynamicSharedMemorySize, anaSm);
    cudaFuncSetAttribute(anaL4,   cudaFuncAttributeMaxDynamicSharedMemorySize, anaL4Sm);
    cudaFuncSetAttribute(synL4,   cudaFuncAttributeMaxDynamicSharedMemorySize, synL4Sm);

    // forward lowpass chain (even row strides for float2-aligned reads)
    fusedAna<<<dim3(9, 9, 256), 256, anaSm>>>(x, B, 512, 512, 512L * 512,
                                              261, 262, 262L * 262);
    fusedAna<<<dim3(5, 5, 256), 256, anaSm>>>(B, D, 261, 262, 262L * 262,
                                              136, 136, 136L * 136);
    fusedAna<<<dim3(3, 3, 256), 256, anaSm>>>(D, E, 136, 136, 136L * 136,
                                              73, 74, 5476);
    // L4 split (2 blocks per channel)
    anaL4<<<dim3(256, 2), 256, anaL4Sm>>>(E, LL, LH, HL, HH);
    // channel mix (weights read once)
    mixAll<<<dim3(7, 32, 4), 256>>>(LL, LH, HL, HH, ML, MLH, MHL, MHH, wyl, wyh);
    // inverse
    synL4<<<256, 512, synL4Sm>>>(ML, MLH, MHL, MHH, F);
    fusedSyn<<<dim3(ceilDiv(136, 64), ceilDiv(136, 64), 256), 256>>>(
        F, D, nullptr, 73, 74, 74L * 74, 136);
    fusedSyn<<<dim3(ceilDiv(262, 64), ceilDiv(262, 64), 256), 256>>>(
        D, B, nullptr, 136, 136, 136L * 136, 262);
    fusedSyn<<<dim3(ceilDiv(512, 64), ceilDiv(512, 64), 256), 256>>>(
        B, out, x, 261, 262, 262L * 262, 512);
}